// round 3
// baseline (speedup 1.0000x reference)
#include <cuda_runtime.h>

// Select: fused pairwise sims GEMM + bidirectional sparsemax attention pooling.
// One block per (image i, caption t) pair.
//
// Shapes: imgs [128,64,128] f32, caps [128,64,128] f32, lens int32[128].
// out [128,128] f32: out[i,t] = 0.5*(v2t + t2v).

#define RDIM 64
#define WDIM 64
#define DDIM 128
#define ASTRIDE 132   // padded row stride for A/B staging (floats)
#define TSTRIDE 65    // padded row stride for sims tile (floats)

__global__ __launch_bounds__(256)
void select_kernel(const float* __restrict__ imgs,
                   const float* __restrict__ caps,
                   const int* __restrict__ img_lens,
                   const int* __restrict__ cap_lens,
                   float* __restrict__ out)
{
    const int t = blockIdx.x;   // caption index
    const int i = blockIdx.y;   // image index
    const int tid = threadIdx.x;

    extern __shared__ float sh[];
    float* As     = sh;                       // 64 x 132
    float* Bs     = As + RDIM * ASTRIDE;      // 64 x 132
    float* tile   = Bs + WDIM * ASTRIDE;      // 64 x 65 (masked sims)
    float* rowdot = tile + RDIM * TSTRIDE;    // 64
    float* coldot = rowdot + RDIM;            // 64
    float* red    = coldot + WDIM;            // 2

    const int ilen = img_lens[i];
    const int tlen = cap_lens[t];

    // ---- Stage imgs[i] and caps[t] into shared (coalesced float4) ----
    const float4* gA = (const float4*)(imgs + (size_t)i * RDIM * DDIM);
    const float4* gB = (const float4*)(caps + (size_t)t * WDIM * DDIM);
#pragma unroll
    for (int e = tid; e < RDIM * DDIM / 4; e += 256) {
        int r = e >> 5, c4 = e & 31;   // 32 float4 per row of 128
        *(float4*)&As[r * ASTRIDE + c4 * 4] = gA[e];
        *(float4*)&Bs[r * ASTRIDE + c4 * 4] = gB[e];
    }
    __syncthreads();

    // ---- 64x64x128 GEMM, 4x4 register microtile per thread ----
    const int tx = tid & 15, ty = tid >> 4;
    const int k0 = ty * 4, l0 = tx * 4;
    float acc[4][4];
#pragma unroll
    for (int kk = 0; kk < 4; kk++)
#pragma unroll
        for (int ll = 0; ll < 4; ll++) acc[kk][ll] = 0.0f;

#pragma unroll 4
    for (int d4 = 0; d4 < DDIM / 4; ++d4) {
        float4 a[4], b[4];
#pragma unroll
        for (int kk = 0; kk < 4; kk++)
            a[kk] = *(const float4*)&As[(k0 + kk) * ASTRIDE + d4 * 4];
#pragma unroll
        for (int ll = 0; ll < 4; ll++)
            b[ll] = *(const float4*)&Bs[(l0 + ll) * ASTRIDE + d4 * 4];
#pragma unroll
        for (int kk = 0; kk < 4; kk++)
#pragma unroll
            for (int ll = 0; ll < 4; ll++) {
                acc[kk][ll] += a[kk].x * b[ll].x;
                acc[kk][ll] += a[kk].y * b[ll].y;
                acc[kk][ll] += a[kk].z * b[ll].z;
                acc[kk][ll] += a[kk].w * b[ll].w;
            }
    }

    // ---- Apply mask (-1.0 fill) and write sims tile ----
#pragma unroll
    for (int kk = 0; kk < 4; kk++)
#pragma unroll
        for (int ll = 0; ll < 4; ll++) {
            int k = k0 + kk, l = l0 + ll;
            tile[k * TSTRIDE + l] = (k < ilen && l < tlen) ? acc[kk][ll] : -1.0f;
        }
    __syncthreads();

    // ---- Sparsemax (Michelot) per row (threads 0..63) and per column (64..127) ----
    if (tid < 128) {
        float z[64];
        if (tid < 64) {
            const float* rp = &tile[tid * TSTRIDE];
#pragma unroll
            for (int j = 0; j < 64; j++) z[j] = rp[j];
        } else {
            const float* cp = &tile[tid - 64];
#pragma unroll
            for (int j = 0; j < 64; j++) z[j] = cp[j * TSTRIDE];
        }

        // tau_0 from full support
        float s0 = 0.f, s1 = 0.f, s2 = 0.f, s3 = 0.f;
#pragma unroll
        for (int j = 0; j < 64; j += 4) {
            s0 += z[j]; s1 += z[j + 1]; s2 += z[j + 2]; s3 += z[j + 3];
        }
        float tau = ((s0 + s1) + (s2 + s3) - 1.0f) * (1.0f / 64.0f);

        // Michelot: support only shrinks; tau monotone non-decreasing; exact fixed point.
        int cprev = 64;
#pragma unroll 1
        for (int it = 0; it < 64; ++it) {
            float t0 = 0.f, t1 = 0.f, t2 = 0.f, t3 = 0.f;
            int c0 = 0, c1 = 0, c2 = 0, c3 = 0;
#pragma unroll
            for (int j = 0; j < 64; j += 4) {
                if (z[j]     > tau) { t0 += z[j];     c0++; }
                if (z[j + 1] > tau) { t1 += z[j + 1]; c1++; }
                if (z[j + 2] > tau) { t2 += z[j + 2]; c2++; }
                if (z[j + 3] > tau) { t3 += z[j + 3]; c3++; }
            }
            int c = (c0 + c1) + (c2 + c3);
            if (c >= cprev) break;            // converged (equal set) / fp-safety
            tau = ((t0 + t1) + (t2 + t3) - 1.0f) / (float)c;
            cprev = c;
        }

        // sum_j max(z_j - tau, 0) * z_j
        float d0 = 0.f, d1 = 0.f, d2 = 0.f, d3 = 0.f;
#pragma unroll
        for (int j = 0; j < 64; j += 4) {
            d0 += fmaxf(z[j]     - tau, 0.0f) * z[j];
            d1 += fmaxf(z[j + 1] - tau, 0.0f) * z[j + 1];
            d2 += fmaxf(z[j + 2] - tau, 0.0f) * z[j + 2];
            d3 += fmaxf(z[j + 3] - tau, 0.0f) * z[j + 3];
        }
        float dot = (d0 + d1) + (d2 + d3);
        if (tid < 64) rowdot[tid] = dot;
        else          coldot[tid - 64] = dot;
    }
    __syncthreads();

    // ---- Weighted marginals: v2t (warp0 over rows), t2v (warp1 over cols) ----
    if (tid < 64) {
        float v;
        if (tid < 32) {
            float wi = 1.0f / (float)ilen;
            float a = (tid      < ilen) ? rowdot[tid]      * wi : 0.0f;
            float b = (tid + 32 < ilen) ? rowdot[tid + 32] * wi : 0.0f;
            v = a + b;
        } else {
            int l = tid - 32;
            float wt = 1.0f / (float)tlen;
            float a = (l      < tlen) ? coldot[l]      * wt : 0.0f;
            float b = (l + 32 < tlen) ? coldot[l + 32] * wt : 0.0f;
            v = a + b;
        }
#pragma unroll
        for (int o = 16; o > 0; o >>= 1) v += __shfl_xor_sync(0xffffffffu, v, o);
        if ((tid & 31) == 0) red[tid >> 5] = v;
    }
    __syncthreads();

    if (tid == 0) out[i * 128 + t] = 0.5f * (red[0] + red[1]);
}

extern "C" void kernel_launch(void* const* d_in, const int* in_sizes, int n_in,
                              void* d_out, int out_size)
{
    // metadata order: img_cls, imgs, cap_cls, caps, img_lens, cap_lens
    const float* imgs = (const float*)d_in[1];
    const float* caps = (const float*)d_in[3];
    const int* img_lens = (const int*)d_in[4];
    const int* cap_lens = (const int*)d_in[5];
    float* out = (float*)d_out;

    const size_t smem = (size_t)(2 * RDIM * ASTRIDE + RDIM * TSTRIDE + RDIM + WDIM + 2) * sizeof(float);

    static bool attr_done = false;
    if (!attr_done) {
        (void)cudaFuncSetAttribute(select_kernel,
                                   cudaFuncAttributeMaxDynamicSharedMemorySize, (int)smem);
        attr_done = true;
    }

    dim3 grid(128, 128);
    select_kernel<<<grid, 256, smem>>>(imgs, caps, img_lens, cap_lens, out);
}

// round 5
// speedup vs baseline: 1.8811x; 1.8811x over previous
#include <cuda_runtime.h>

// Select: fused pairwise sims GEMM + bidirectional sparsemax attention pooling.
// One block per (image i, caption t) pair.
//
// Shapes: imgs [128,64,128] f32, caps [128,64,128] f32, lens int32[128].
// out [128,128] f32: out[i,t] = 0.5*(v2t + t2v).
//
// R4: strided microtile ownership (l = tx + 16*ll) -> conflict-free LDS.128
//     on B; sims tile aliased onto As (dead after GEMM) -> 68KB smem, 3 blk/SM.

#define RDIM 64
#define WDIM 64
#define DDIM 128
#define ASTRIDE 132   // padded row stride for A/B staging (floats), 16B-aligned rows
#define TSTRIDE 65    // padded row stride for sims tile (floats)

__global__ __launch_bounds__(256)
void select_kernel(const float* __restrict__ imgs,
                   const float* __restrict__ caps,
                   const int* __restrict__ img_lens,
                   const int* __restrict__ cap_lens,
                   float* __restrict__ out)
{
    const int t = blockIdx.x;   // caption index
    const int i = blockIdx.y;   // image index
    const int tid = threadIdx.x;

    extern __shared__ float sh[];
    float* As     = sh;                       // 64 x 132
    float* Bs     = As + RDIM * ASTRIDE;      // 64 x 132
    float* tile   = As;                       // 64 x 65, ALIASES As (dead after GEMM)
    float* rowdot = Bs + WDIM * ASTRIDE;      // 64
    float* coldot = rowdot + RDIM;            // 64
    float* red    = coldot + WDIM;            // 2

    const int ilen = img_lens[i];
    const int tlen = cap_lens[t];

    // ---- Stage imgs[i] and caps[t] into shared (coalesced float4) ----
    const float4* gA = (const float4*)(imgs + (size_t)i * RDIM * DDIM);
    const float4* gB = (const float4*)(caps + (size_t)t * WDIM * DDIM);
#pragma unroll
    for (int e = tid; e < RDIM * DDIM / 4; e += 256) {
        int r = e >> 5, c4 = e & 31;   // 32 float4 per row of 128
        *(float4*)&As[r * ASTRIDE + c4 * 4] = gA[e];
        *(float4*)&Bs[r * ASTRIDE + c4 * 4] = gB[e];
    }
    __syncthreads();

    // ---- 64x64x128 GEMM, 4x4 register microtile per thread ----
    // STRIDED ownership: thread (tx,ty) owns rows k = ty + 16*kk, cols l = tx + 16*ll.
    // Neighbor tx reads rows ASTRIDE floats apart: 16B-group = 33*tx mod 8 -> all
    // distinct within each 8-lane LDS.128 phase -> conflict-free. A reads broadcast.
    const int tx = tid & 15, ty = tid >> 4;
    float acc[4][4];
#pragma unroll
    for (int kk = 0; kk < 4; kk++)
#pragma unroll
        for (int ll = 0; ll < 4; ll++) acc[kk][ll] = 0.0f;

#pragma unroll 4
    for (int d4 = 0; d4 < DDIM / 4; ++d4) {
        float4 a[4], b[4];
#pragma unroll
        for (int kk = 0; kk < 4; kk++)
            a[kk] = *(const float4*)&As[(ty + 16 * kk) * ASTRIDE + d4 * 4];
#pragma unroll
        for (int ll = 0; ll < 4; ll++)
            b[ll] = *(const float4*)&Bs[(tx + 16 * ll) * ASTRIDE + d4 * 4];
#pragma unroll
        for (int kk = 0; kk < 4; kk++)
#pragma unroll
            for (int ll = 0; ll < 4; ll++) {
                acc[kk][ll] += a[kk].x * b[ll].x;
                acc[kk][ll] += a[kk].y * b[ll].y;
                acc[kk][ll] += a[kk].z * b[ll].z;
                acc[kk][ll] += a[kk].w * b[ll].w;
            }
    }

    __syncthreads();   // all reads of As complete before tile (aliased) is written

    // ---- Apply mask (-1.0 fill) and write sims tile ----
#pragma unroll
    for (int kk = 0; kk < 4; kk++)
#pragma unroll
        for (int ll = 0; ll < 4; ll++) {
            int k = ty + 16 * kk, l = tx + 16 * ll;
            tile[k * TSTRIDE + l] = (k < ilen && l < tlen) ? acc[kk][ll] : -1.0f;
        }
    __syncthreads();

    // ---- Sparsemax (Michelot) per row (threads 0..63) and per column (64..127) ----
    if (tid < 128) {
        float z[64];
        if (tid < 64) {
            const float* rp = &tile[tid * TSTRIDE];
#pragma unroll
            for (int j = 0; j < 64; j++) z[j] = rp[j];
        } else {
            const float* cp = &tile[tid - 64];
#pragma unroll
            for (int j = 0; j < 64; j++) z[j] = cp[j * TSTRIDE];
        }

        // tau_0 from full support
        float s0 = 0.f, s1 = 0.f, s2 = 0.f, s3 = 0.f;
#pragma unroll
        for (int j = 0; j < 64; j += 4) {
            s0 += z[j]; s1 += z[j + 1]; s2 += z[j + 2]; s3 += z[j + 3];
        }
        float tau = ((s0 + s1) + (s2 + s3) - 1.0f) * (1.0f / 64.0f);

        // Michelot: support only shrinks; exact sparsemax fixed point.
        int cprev = 64;
#pragma unroll 1
        for (int it = 0; it < 64; ++it) {
            float t0 = 0.f, t1 = 0.f, t2 = 0.f, t3 = 0.f;
            int c0 = 0, c1 = 0, c2 = 0, c3 = 0;
#pragma unroll
            for (int j = 0; j < 64; j += 4) {
                if (z[j]     > tau) { t0 += z[j];     c0++; }
                if (z[j + 1] > tau) { t1 += z[j + 1]; c1++; }
                if (z[j + 2] > tau) { t2 += z[j + 2]; c2++; }
                if (z[j + 3] > tau) { t3 += z[j + 3]; c3++; }
            }
            int c = (c0 + c1) + (c2 + c3);
            if (c >= cprev) break;            // converged (equal set) / fp-safety
            tau = ((t0 + t1) + (t2 + t3) - 1.0f) / (float)c;
            cprev = c;
        }

        // sum_j max(z_j - tau, 0) * z_j
        float d0 = 0.f, d1 = 0.f, d2 = 0.f, d3 = 0.f;
#pragma unroll
        for (int j = 0; j < 64; j += 4) {
            d0 += fmaxf(z[j]     - tau, 0.0f) * z[j];
            d1 += fmaxf(z[j + 1] - tau, 0.0f) * z[j + 1];
            d2 += fmaxf(z[j + 2] - tau, 0.0f) * z[j + 2];
            d3 += fmaxf(z[j + 3] - tau, 0.0f) * z[j + 3];
        }
        float dot = (d0 + d1) + (d2 + d3);
        if (tid < 64) rowdot[tid] = dot;
        else          coldot[tid - 64] = dot;
    }
    __syncthreads();

    // ---- Weighted marginals: v2t (warp0 over rows), t2v (warp1 over cols) ----
    if (tid < 64) {
        float v;
        if (tid < 32) {
            float wi = 1.0f / (float)ilen;
            float a = (tid      < ilen) ? rowdot[tid]      * wi : 0.0f;
            float b = (tid + 32 < ilen) ? rowdot[tid + 32] * wi : 0.0f;
            v = a + b;
        } else {
            int l = tid - 32;
            float wt = 1.0f / (float)tlen;
            float a = (l      < tlen) ? coldot[l]      * wt : 0.0f;
            float b = (l + 32 < tlen) ? coldot[l + 32] * wt : 0.0f;
            v = a + b;
        }
#pragma unroll
        for (int o = 16; o > 0; o >>= 1) v += __shfl_xor_sync(0xffffffffu, v, o);
        if ((tid & 31) == 0) red[tid >> 5] = v;
    }
    __syncthreads();

    if (tid == 0) out[i * 128 + t] = 0.5f * (red[0] + red[1]);
}

extern "C" void kernel_launch(void* const* d_in, const int* in_sizes, int n_in,
                              void* d_out, int out_size)
{
    // metadata order: img_cls, imgs, cap_cls, caps, img_lens, cap_lens
    const float* imgs = (const float*)d_in[1];
    const float* caps = (const float*)d_in[3];
    const int* img_lens = (const int*)d_in[4];
    const int* cap_lens = (const int*)d_in[5];
    float* out = (float*)d_out;

    const size_t smem = (size_t)(2 * RDIM * ASTRIDE + RDIM + WDIM + 2) * sizeof(float);

    static bool attr_done = false;
    if (!attr_done) {
        (void)cudaFuncSetAttribute(select_kernel,
                                   cudaFuncAttributeMaxDynamicSharedMemorySize, (int)smem);
        attr_done = true;
    }

    dim3 grid(128, 128);
    select_kernel<<<grid, 256, smem>>>(imgs, caps, img_lens, cap_lens, out);
}

// round 8
// speedup vs baseline: 3.0340x; 1.6129x over previous
#include <cuda_runtime.h>
#include <cuda_bf16.h>
#include <cstdint>

// Select: per-pair sims GEMM on tensor cores (portable mma.sync bf16, hi/lo
// split, fp32 accum) + bidirectional sparsemax pooling.
// One block (256 thr) per (image i, caption t) pair; grid (128,128).

#define KS 136        // padded bf16 row stride (272B rows -> conflict-free ldmatrix)
#define TSTRIDE 65

// smem byte offsets
#define SM_AH   0
#define SM_AL   17408
#define SM_BH   34816
#define SM_BL   52224
#define SM_DOT  69632          // rowdot[64] f32
#define SM_COL  69888          // coldot[64] f32
#define SM_RED  70144          // red[2] f32
#define SM_TOTAL 70400
#define SM_TILE 0              // f32 [64][65] aliased over AH/AL (dead after MMA)

static __device__ __forceinline__ uint32_t smem_u32(const void* p) {
    uint32_t a;
    asm("{ .reg .u64 t; cvta.to.shared.u64 t, %1; cvt.u32.u64 %0, t; }"
        : "=r"(a) : "l"(p));
    return a;
}

#define LDSM_X4(r0, r1, r2, r3, addr)                                          \
    asm volatile("ldmatrix.sync.aligned.m8n8.x4.shared.b16 {%0,%1,%2,%3}, [%4];" \
                 : "=r"(r0), "=r"(r1), "=r"(r2), "=r"(r3) : "r"(addr))

#define MMA16816(c, a, b0v, b1v)                                               \
    asm volatile("mma.sync.aligned.m16n8k16.row.col.f32.bf16.bf16.f32 "        \
                 "{%0,%1,%2,%3}, {%4,%5,%6,%7}, {%8,%9}, {%0,%1,%2,%3};"       \
                 : "+f"((c)[0]), "+f"((c)[1]), "+f"((c)[2]), "+f"((c)[3])      \
                 : "r"((a)[0]), "r"((a)[1]), "r"((a)[2]), "r"((a)[3]),         \
                   "r"(b0v), "r"(b1v))

// pack fp32x4 -> bf16 hi quad + lo quad
static __device__ __forceinline__ void split4(float4 v, uint2& hi, uint2& lo) {
    __nv_bfloat16 h0 = __float2bfloat16(v.x), h1 = __float2bfloat16(v.y);
    __nv_bfloat16 h2 = __float2bfloat16(v.z), h3 = __float2bfloat16(v.w);
    __nv_bfloat16 l0 = __float2bfloat16(v.x - __bfloat162float(h0));
    __nv_bfloat16 l1 = __float2bfloat16(v.y - __bfloat162float(h1));
    __nv_bfloat16 l2 = __float2bfloat16(v.z - __bfloat162float(h2));
    __nv_bfloat16 l3 = __float2bfloat16(v.w - __bfloat162float(h3));
    hi.x = ((uint32_t)__bfloat16_as_ushort(h1) << 16) | __bfloat16_as_ushort(h0);
    hi.y = ((uint32_t)__bfloat16_as_ushort(h3) << 16) | __bfloat16_as_ushort(h2);
    lo.x = ((uint32_t)__bfloat16_as_ushort(l1) << 16) | __bfloat16_as_ushort(l0);
    lo.y = ((uint32_t)__bfloat16_as_ushort(l3) << 16) | __bfloat16_as_ushort(l2);
}

__global__ __launch_bounds__(256, 2)
void select_mma_kernel(const float* __restrict__ imgs,
                       const float* __restrict__ caps,
                       const int* __restrict__ img_lens,
                       const int* __restrict__ cap_lens,
                       float* __restrict__ out)
{
    extern __shared__ char smc[];
    const int t = blockIdx.x;   // caption
    const int i = blockIdx.y;   // image
    const int tid = threadIdx.x;
    const int wid = tid >> 5, lane = tid & 31;
    const uint32_t sb = smem_u32(smc);

    const int ilen = img_lens[i];
    const int tlen = cap_lens[t];

    // ---- Stage imgs[i] / caps[t] as bf16 hi/lo, padded K-major ----
    {
        const float4* gA = (const float4*)(imgs + (size_t)i * 64 * 128);
        const float4* gB = (const float4*)(caps + (size_t)t * 64 * 128);
#pragma unroll
        for (int e = tid; e < 2048; e += 256) {
            int row = e >> 5, col = (e & 31) * 4;
            uint32_t off = (uint32_t)(row * KS + col) * 2;
            uint2 hi, lo;
            split4(gA[e], hi, lo);
            *(uint2*)(smc + SM_AH + off) = hi;
            *(uint2*)(smc + SM_AL + off) = lo;
            split4(gB[e], hi, lo);
            *(uint2*)(smc + SM_BH + off) = hi;
            *(uint2*)(smc + SM_BL + off) = lo;
        }
    }
    __syncthreads();

    // ---- GEMM: 8 warps = 4(m) x 2(n); warp tile 16x32; K=128 in 8 steps ----
    const int mw = wid & 3, nw = wid >> 2;
    const int mrow = mw * 16, n0 = nw * 32;

    // ldmatrix lane addressing (element offsets, bf16)
    const int arow = mrow + (lane & 15);
    const int acol = (lane >> 4) << 3;
    const uint32_t aoff = (uint32_t)(arow * KS + acol) * 2;
    const int brow = n0 + ((lane >> 4) << 3) + (lane & 7);
    const int bcol = ((lane >> 3) & 1) << 3;
    const uint32_t boff = (uint32_t)(brow * KS + bcol) * 2;

    float c[4][4];
#pragma unroll
    for (int j = 0; j < 4; j++)
#pragma unroll
        for (int r = 0; r < 4; r++) c[j][r] = 0.0f;

#pragma unroll
    for (int kk = 0; kk < 8; ++kk) {
        const uint32_t kb = (uint32_t)kk * 32;  // 16 bf16 = 32 bytes
        uint32_t ah[4], al[4], bh[8], bl[8];
        LDSM_X4(ah[0], ah[1], ah[2], ah[3], sb + SM_AH + aoff + kb);
        LDSM_X4(al[0], al[1], al[2], al[3], sb + SM_AL + aoff + kb);
        LDSM_X4(bh[0], bh[1], bh[2], bh[3], sb + SM_BH + boff + kb);
        LDSM_X4(bh[4], bh[5], bh[6], bh[7], sb + SM_BH + boff + 16 * KS * 2 + kb);
        LDSM_X4(bl[0], bl[1], bl[2], bl[3], sb + SM_BL + boff + kb);
        LDSM_X4(bl[4], bl[5], bl[6], bl[7], sb + SM_BL + boff + 16 * KS * 2 + kb);
#pragma unroll
        for (int j = 0; j < 4; ++j) {
            MMA16816(c[j], ah, bh[j * 2], bh[j * 2 + 1]);   // Ah*Bh
            MMA16816(c[j], ah, bl[j * 2], bl[j * 2 + 1]);   // Ah*Bl
            MMA16816(c[j], al, bh[j * 2], bh[j * 2 + 1]);   // Al*Bh
        }
    }
    __syncthreads();   // smem A/B reads complete; tile alias safe

    // ---- Scatter masked fragments into f32 tile [64][65] ----
    {
        float* tile = (float*)(smc + SM_TILE);
        const int rowg = lane >> 2, colg = (lane & 3) * 2;
#pragma unroll
        for (int j = 0; j < 4; ++j) {
            const int r0 = mrow + rowg, cl = n0 + j * 8 + colg;
            const bool cm0 = cl < tlen, cm1 = (cl + 1) < tlen;
            tile[r0 * TSTRIDE + cl]           = (r0 < ilen && cm0) ? c[j][0] : -1.0f;
            tile[r0 * TSTRIDE + cl + 1]       = (r0 < ilen && cm1) ? c[j][1] : -1.0f;
            tile[(r0 + 8) * TSTRIDE + cl]     = ((r0 + 8) < ilen && cm0) ? c[j][2] : -1.0f;
            tile[(r0 + 8) * TSTRIDE + cl + 1] = ((r0 + 8) < ilen && cm1) ? c[j][3] : -1.0f;
        }
    }
    __syncthreads();

    // ---- Sparsemax (Michelot, exact) per row (0..63) / per column (64..127) ----
    if (tid < 128) {
        const float* tile = (const float*)(smc + SM_TILE);
        float z[64];
        if (tid < 64) {
            const float* rp = &tile[tid * TSTRIDE];
#pragma unroll
            for (int j = 0; j < 64; j++) z[j] = rp[j];
        } else {
            const float* cp = &tile[tid - 64];
#pragma unroll
            for (int j = 0; j < 64; j++) z[j] = cp[j * TSTRIDE];
        }

        float s0 = 0.f, s1 = 0.f, s2 = 0.f, s3 = 0.f;
#pragma unroll
        for (int j = 0; j < 64; j += 4) {
            s0 += z[j]; s1 += z[j + 1]; s2 += z[j + 2]; s3 += z[j + 3];
        }
        float tau = ((s0 + s1) + (s2 + s3) - 1.0f) * (1.0f / 64.0f);

        int cprev = 64;
#pragma unroll 1
        for (int it = 0; it < 64; ++it) {
            float t0 = 0.f, t1 = 0.f, t2 = 0.f, t3 = 0.f;
            int c0 = 0, c1 = 0, c2 = 0, c3 = 0;
#pragma unroll
            for (int j = 0; j < 64; j += 4) {
                if (z[j]     > tau) { t0 += z[j];     c0++; }
                if (z[j + 1] > tau) { t1 += z[j + 1]; c1++; }
                if (z[j + 2] > tau) { t2 += z[j + 2]; c2++; }
                if (z[j + 3] > tau) { t3 += z[j + 3]; c3++; }
            }
            int cc = (c0 + c1) + (c2 + c3);
            if (cc >= cprev) break;
            tau = ((t0 + t1) + (t2 + t3) - 1.0f) / (float)cc;
            cprev = cc;
        }

        float d0 = 0.f, d1 = 0.f, d2 = 0.f, d3 = 0.f;
#pragma unroll
        for (int j = 0; j < 64; j += 4) {
            d0 += fmaxf(z[j]     - tau, 0.0f) * z[j];
            d1 += fmaxf(z[j + 1] - tau, 0.0f) * z[j + 1];
            d2 += fmaxf(z[j + 2] - tau, 0.0f) * z[j + 2];
            d3 += fmaxf(z[j + 3] - tau, 0.0f) * z[j + 3];
        }
        float dot = (d0 + d1) + (d2 + d3);
        if (tid < 64) ((float*)(smc + SM_DOT))[tid] = dot;
        else          ((float*)(smc + SM_COL))[tid - 64] = dot;
    }
    __syncthreads();

    // ---- Weighted marginals ----
    if (tid < 64) {
        float v;
        if (tid < 32) {
            const float* rd = (const float*)(smc + SM_DOT);
            float wi = 1.0f / (float)ilen;
            float a = (tid      < ilen) ? rd[tid]      * wi : 0.0f;
            float b = (tid + 32 < ilen) ? rd[tid + 32] * wi : 0.0f;
            v = a + b;
        } else {
            const float* cd = (const float*)(smc + SM_COL);
            int l = tid - 32;
            float wt = 1.0f / (float)tlen;
            float a = (l      < tlen) ? cd[l]      * wt : 0.0f;
            float b = (l + 32 < tlen) ? cd[l + 32] * wt : 0.0f;
            v = a + b;
        }
#pragma unroll
        for (int o = 16; o > 0; o >>= 1) v += __shfl_xor_sync(0xffffffffu, v, o);
        if ((tid & 31) == 0) ((float*)(smc + SM_RED))[tid >> 5] = v;
    }
    __syncthreads();

    if (tid == 0) {
        const float* red = (const float*)(smc + SM_RED);
        out[i * 128 + t] = 0.5f * (red[0] + red[1]);
    }
}

extern "C" void kernel_launch(void* const* d_in, const int* in_sizes, int n_in,
                              void* d_out, int out_size)
{
    // metadata order: img_cls, imgs, cap_cls, caps, img_lens, cap_lens
    const float* imgs = (const float*)d_in[1];
    const float* caps = (const float*)d_in[3];
    const int* img_lens = (const int*)d_in[4];
    const int* cap_lens = (const int*)d_in[5];
    float* out = (float*)d_out;

    static bool attr_done = false;
    if (!attr_done) {
        (void)cudaFuncSetAttribute(select_mma_kernel,
                                   cudaFuncAttributeMaxDynamicSharedMemorySize, SM_TOTAL);
        attr_done = true;
    }

    dim3 grid(128, 128);
    select_mma_kernel<<<grid, 256, SM_TOTAL>>>(imgs, caps, img_lens, cap_lens, out);
}

// round 9
// speedup vs baseline: 4.1926x; 1.3819x over previous
#include <cuda_runtime.h>
#include <cuda_bf16.h>
#include <cstdint>

// Select: per-pair sims GEMM on tensor cores (mma.sync bf16 hi/lo split, fp32
// accum) + bidirectional sparsemax pooling.
// R9: bf16 hi/lo planes precomputed ONCE by a prologue kernel into __device__
//     scratch (was re-converted 128x per tensor); staging via cp.async.
//     Sparsemax now 2 threads/vector (all 256 threads busy, shfl-combined).

#define KS 136        // padded bf16 row stride (272B rows)
#define TSTRIDE 65

// smem byte offsets
#define SM_AH   0
#define SM_AL   17408
#define SM_BH   34816
#define SM_BL   52224
#define SM_DOT  69632          // rowdot[64] f32
#define SM_COL  69888          // coldot[64] f32
#define SM_RED  70144          // red[2] f32
#define SM_TOTAL 70400
#define SM_TILE 0              // f32 [64][65] aliased over AH/AL (dead after MMA)

// ---- precomputed bf16 hi/lo planes: [tensor][64*128] bf16 as uint4 chunks ----
// per tensor-slice: 64*128 bf16 = 16KB = 1024 uint4. 128 slices each.
__device__ uint4 g_ih[131072];   // imgs hi  (2MB)
__device__ uint4 g_il[131072];   // imgs lo
__device__ uint4 g_ch[131072];   // caps hi
__device__ uint4 g_cl[131072];   // caps lo

static __device__ __forceinline__ uint32_t smem_u32(const void* p) {
    uint32_t a;
    asm("{ .reg .u64 t; cvta.to.shared.u64 t, %1; cvt.u32.u64 %0, t; }"
        : "=r"(a) : "l"(p));
    return a;
}

#define LDSM_X4(r0, r1, r2, r3, addr)                                          \
    asm volatile("ldmatrix.sync.aligned.m8n8.x4.shared.b16 {%0,%1,%2,%3}, [%4];" \
                 : "=r"(r0), "=r"(r1), "=r"(r2), "=r"(r3) : "r"(addr))

#define MMA16816(c, a, b0v, b1v)                                               \
    asm volatile("mma.sync.aligned.m16n8k16.row.col.f32.bf16.bf16.f32 "        \
                 "{%0,%1,%2,%3}, {%4,%5,%6,%7}, {%8,%9}, {%0,%1,%2,%3};"       \
                 : "+f"((c)[0]), "+f"((c)[1]), "+f"((c)[2]), "+f"((c)[3])      \
                 : "r"((a)[0]), "r"((a)[1]), "r"((a)[2]), "r"((a)[3]),         \
                   "r"(b0v), "r"(b1v))

static __device__ __forceinline__ void split4(float4 v, uint2& hi, uint2& lo) {
    __nv_bfloat16 h0 = __float2bfloat16(v.x), h1 = __float2bfloat16(v.y);
    __nv_bfloat16 h2 = __float2bfloat16(v.z), h3 = __float2bfloat16(v.w);
    __nv_bfloat16 l0 = __float2bfloat16(v.x - __bfloat162float(h0));
    __nv_bfloat16 l1 = __float2bfloat16(v.y - __bfloat162float(h1));
    __nv_bfloat16 l2 = __float2bfloat16(v.z - __bfloat162float(h2));
    __nv_bfloat16 l3 = __float2bfloat16(v.w - __bfloat162float(h3));
    hi.x = ((uint32_t)__bfloat16_as_ushort(h1) << 16) | __bfloat16_as_ushort(h0);
    hi.y = ((uint32_t)__bfloat16_as_ushort(h3) << 16) | __bfloat16_as_ushort(h2);
    lo.x = ((uint32_t)__bfloat16_as_ushort(l1) << 16) | __bfloat16_as_ushort(l0);
    lo.y = ((uint32_t)__bfloat16_as_ushort(l3) << 16) | __bfloat16_as_ushort(l2);
}

// ---- Prologue: fp32 -> bf16 hi/lo planes, once per launch ----
__global__ __launch_bounds__(256)
void split_kernel(const float4* __restrict__ imgs, const float4* __restrict__ caps)
{
    int idx = blockIdx.x * 256 + threadIdx.x;        // 0..262143
    const bool isimg = idx < 131072;
    int e = isimg ? idx : idx - 131072;
    const float4* src = isimg ? imgs : caps;
    uint4* hp = isimg ? g_ih : g_ch;
    uint4* lp = isimg ? g_il : g_cl;
    float4 v0 = src[2 * e], v1 = src[2 * e + 1];
    uint2 h0, l0, h1, l1;
    split4(v0, h0, l0);
    split4(v1, h1, l1);
    hp[e] = make_uint4(h0.x, h0.y, h1.x, h1.y);
    lp[e] = make_uint4(l0.x, l0.y, l1.x, l1.y);
}

__global__ __launch_bounds__(256, 2)
void select_mma_kernel(const int* __restrict__ img_lens,
                       const int* __restrict__ cap_lens,
                       float* __restrict__ out)
{
    extern __shared__ char smc[];
    const int t = blockIdx.x;   // caption
    const int i = blockIdx.y;   // image
    const int tid = threadIdx.x;
    const int wid = tid >> 5, lane = tid & 31;
    const uint32_t sb = smem_u32(smc);

    const int ilen = img_lens[i];
    const int tlen = cap_lens[t];

    // ---- Stage precomputed bf16 hi/lo planes via cp.async (pure copy) ----
    {
        const uint4* planes[4] = { g_ih + i * 1024, g_il + i * 1024,
                                   g_ch + t * 1024, g_cl + t * 1024 };
        const uint32_t doff[4] = { SM_AH, SM_AL, SM_BH, SM_BL };
#pragma unroll
        for (int p = 0; p < 4; ++p) {
            unsigned long long gb =
                (unsigned long long)__cvta_generic_to_global(planes[p]);
#pragma unroll
            for (int k = 0; k < 4; ++k) {
                int c = tid + k * 256;                 // 0..1023
                uint32_t row = (uint32_t)c >> 4, sub = (uint32_t)c & 15;
                uint32_t sa = sb + doff[p] + row * (KS * 2) + sub * 16;
                asm volatile("cp.async.cg.shared.global [%0], [%1], 16;"
                             :: "r"(sa), "l"(gb + (unsigned long long)c * 16)
                             : "memory");
            }
        }
        asm volatile("cp.async.commit_group;" ::: "memory");
        asm volatile("cp.async.wait_group 0;" ::: "memory");
    }
    __syncthreads();

    // ---- GEMM: 8 warps = 4(m) x 2(n); warp tile 16x32; K=128 in 8 steps ----
    const int mw = wid & 3, nw = wid >> 2;
    const int mrow = mw * 16, n0 = nw * 32;

    const int arow = mrow + (lane & 15);
    const int acol = (lane >> 4) << 3;
    const uint32_t aoff = (uint32_t)(arow * KS + acol) * 2;
    const int brow = n0 + ((lane >> 4) << 3) + (lane & 7);
    const int bcol = ((lane >> 3) & 1) << 3;
    const uint32_t boff = (uint32_t)(brow * KS + bcol) * 2;

    float c[4][4];
#pragma unroll
    for (int j = 0; j < 4; j++)
#pragma unroll
        for (int r = 0; r < 4; r++) c[j][r] = 0.0f;

#pragma unroll
    for (int kk = 0; kk < 8; ++kk) {
        const uint32_t kb = (uint32_t)kk * 32;
        uint32_t ah[4], al[4], bh[8], bl[8];
        LDSM_X4(ah[0], ah[1], ah[2], ah[3], sb + SM_AH + aoff + kb);
        LDSM_X4(al[0], al[1], al[2], al[3], sb + SM_AL + aoff + kb);
        LDSM_X4(bh[0], bh[1], bh[2], bh[3], sb + SM_BH + boff + kb);
        LDSM_X4(bh[4], bh[5], bh[6], bh[7], sb + SM_BH + boff + 16 * KS * 2 + kb);
        LDSM_X4(bl[0], bl[1], bl[2], bl[3], sb + SM_BL + boff + kb);
        LDSM_X4(bl[4], bl[5], bl[6], bl[7], sb + SM_BL + boff + 16 * KS * 2 + kb);
#pragma unroll
        for (int j = 0; j < 4; ++j) {
            MMA16816(c[j], ah, bh[j * 2], bh[j * 2 + 1]);   // Ah*Bh
            MMA16816(c[j], ah, bl[j * 2], bl[j * 2 + 1]);   // Ah*Bl
            MMA16816(c[j], al, bh[j * 2], bh[j * 2 + 1]);   // Al*Bh
        }
    }
    __syncthreads();   // smem A/B reads complete; tile alias safe

    // ---- Scatter masked fragments into f32 tile [64][65] ----
    {
        float* tile = (float*)(smc + SM_TILE);
        const int rowg = lane >> 2, colg = (lane & 3) * 2;
#pragma unroll
        for (int j = 0; j < 4; ++j) {
            const int r0 = mrow + rowg, cl = n0 + j * 8 + colg;
            const bool cm0 = cl < tlen, cm1 = (cl + 1) < tlen;
            tile[r0 * TSTRIDE + cl]           = (r0 < ilen && cm0) ? c[j][0] : -1.0f;
            tile[r0 * TSTRIDE + cl + 1]       = (r0 < ilen && cm1) ? c[j][1] : -1.0f;
            tile[(r0 + 8) * TSTRIDE + cl]     = ((r0 + 8) < ilen && cm0) ? c[j][2] : -1.0f;
            tile[(r0 + 8) * TSTRIDE + cl + 1] = ((r0 + 8) < ilen && cm1) ? c[j][3] : -1.0f;
        }
    }
    __syncthreads();

    // ---- Sparsemax (Michelot, exact): 2 threads per vector, all 256 busy ----
    // vec 0..63 = rows (warps 0-3), vec 64..127 = cols (warps 4-7).
    {
        const float* tile = (const float*)(smc + SM_TILE);
        const int vec = tid >> 1, half = tid & 1;
        float z[32];
        if (vec < 64) {
            const float* rp = tile + vec * TSTRIDE + half * 32;
#pragma unroll
            for (int j = 0; j < 32; j++) z[j] = rp[j];
        } else {
            const float* cp = tile + (half * 32) * TSTRIDE + (vec - 64);
#pragma unroll
            for (int j = 0; j < 32; j++) z[j] = cp[j * TSTRIDE];
        }

        // tau_0 from full support (pair-combined)
        float s0 = 0.f, s1 = 0.f, s2 = 0.f, s3 = 0.f;
#pragma unroll
        for (int j = 0; j < 32; j += 4) {
            s0 += z[j]; s1 += z[j + 1]; s2 += z[j + 2]; s3 += z[j + 3];
        }
        float s = (s0 + s1) + (s2 + s3);
        s += __shfl_xor_sync(0xffffffffu, s, 1);
        float tau = (s - 1.0f) * (1.0f / 64.0f);

        // Michelot with warp-uniform exit (shfl-safe)
        int cprev = 64;
        bool done = false;
#pragma unroll 1
        for (int it = 0; it < 64; ++it) {
            float t0 = 0.f, t1 = 0.f;
            float c0 = 0.f, c1 = 0.f;
#pragma unroll
            for (int j = 0; j < 32; j += 2) {
                if (z[j]     > tau) { t0 += z[j];     c0 += 1.0f; }
                if (z[j + 1] > tau) { t1 += z[j + 1]; c1 += 1.0f; }
            }
            float ts = t0 + t1, cs = c0 + c1;
            ts += __shfl_xor_sync(0xffffffffu, ts, 1);
            cs += __shfl_xor_sync(0xffffffffu, cs, 1);
            int cc = (int)cs;
            bool conv = done || (cc >= cprev);
            if (!conv) { tau = (ts - 1.0f) / cs; cprev = cc; }
            done = conv;
            if (__all_sync(0xffffffffu, done)) break;
        }

        // sum_j max(z_j - tau, 0) * z_j (pair-combined)
        float d0 = 0.f, d1 = 0.f, d2 = 0.f, d3 = 0.f;
#pragma unroll
        for (int j = 0; j < 32; j += 4) {
            d0 += fmaxf(z[j]     - tau, 0.0f) * z[j];
            d1 += fmaxf(z[j + 1] - tau, 0.0f) * z[j + 1];
            d2 += fmaxf(z[j + 2] - tau, 0.0f) * z[j + 2];
            d3 += fmaxf(z[j + 3] - tau, 0.0f) * z[j + 3];
        }
        float dot = (d0 + d1) + (d2 + d3);
        dot += __shfl_xor_sync(0xffffffffu, dot, 1);
        if (half == 0) {
            if (vec < 64) ((float*)(smc + SM_DOT))[vec] = dot;
            else          ((float*)(smc + SM_COL))[vec - 64] = dot;
        }
    }
    __syncthreads();

    // ---- Weighted marginals ----
    if (tid < 64) {
        float v;
        if (tid < 32) {
            const float* rd = (const float*)(smc + SM_DOT);
            float wi = 1.0f / (float)ilen;
            float a = (tid      < ilen) ? rd[tid]      * wi : 0.0f;
            float b = (tid + 32 < ilen) ? rd[tid + 32] * wi : 0.0f;
            v = a + b;
        } else {
            const float* cd = (const float*)(smc + SM_COL);
            int l = tid - 32;
            float wt = 1.0f / (float)tlen;
            float a = (l      < tlen) ? cd[l]      * wt : 0.0f;
            float b = (l + 32 < tlen) ? cd[l + 32] * wt : 0.0f;
            v = a + b;
        }
#pragma unroll
        for (int o = 16; o > 0; o >>= 1) v += __shfl_xor_sync(0xffffffffu, v, o);
        if ((tid & 31) == 0) ((float*)(smc + SM_RED))[tid >> 5] = v;
    }
    __syncthreads();

    if (tid == 0) {
        const float* red = (const float*)(smc + SM_RED);
        out[i * 128 + t] = 0.5f * (red[0] + red[1]);
    }
}

extern "C" void kernel_launch(void* const* d_in, const int* in_sizes, int n_in,
                              void* d_out, int out_size)
{
    // metadata order: img_cls, imgs, cap_cls, caps, img_lens, cap_lens
    const float* imgs = (const float*)d_in[1];
    const float* caps = (const float*)d_in[3];
    const int* img_lens = (const int*)d_in[4];
    const int* cap_lens = (const int*)d_in[5];
    float* out = (float*)d_out;

    static bool attr_done = false;
    if (!attr_done) {
        (void)cudaFuncSetAttribute(select_mma_kernel,
                                   cudaFuncAttributeMaxDynamicSharedMemorySize, SM_TOTAL);
        attr_done = true;
    }

    split_kernel<<<1024, 256>>>((const float4*)imgs, (const float4*)caps);
    dim3 grid(128, 128);
    select_mma_kernel<<<grid, 256, SM_TOTAL>>>(img_lens, cap_lens, out);
}